// round 1
// baseline (speedup 1.0000x reference)
#include <cuda_runtime.h>

#define Bb 64
#define Nn 1000
#define FUTc 12
#define Oo 16
#define Hh 128
#define Ee 64
#define Gg 512
#define TSTEPS (Nn * FUTc)

typedef unsigned long long u64;

// Scratch (allocation-free rule: __device__ globals)
__device__ float g_encacc[(size_t)Bb * Nn * Gg];   // per (b,n): enc part of cell0 gates + bias
__device__ float g_nm[Bb * Nn * Oo];               // node means

// ---------- packed fp32x2 helpers ----------
__device__ __forceinline__ void ffma2(u64 &acc, u64 a, u64 b) {
    asm("fma.rn.f32x2 %0, %1, %2, %0;" : "+l"(acc) : "l"(a), "l"(b));
}
__device__ __forceinline__ u64 pack2(float x, float y) {
    u64 r; asm("mov.b64 %0, {%1, %2};" : "=l"(r) : "f"(x), "f"(y)); return r;
}
__device__ __forceinline__ void unpack2(u64 v, float &x, float &y) {
    asm("mov.b64 {%0, %1}, %2;" : "=f"(x), "=f"(y) : "l"(v));
}

// ---------- fast activations ----------
#define LOG2E 1.4426950408889634f
__device__ __forceinline__ float ex2f(float x) { float r; asm("ex2.approx.f32 %0, %1;" : "=f"(r) : "f"(x)); return r; }
__device__ __forceinline__ float rcpf(float x) { float r; asm("rcp.approx.f32 %0, %1;" : "=f"(r) : "f"(x)); return r; }
__device__ __forceinline__ float sigm(float x) { return rcpf(1.f + ex2f(-x * LOG2E)); }
__device__ __forceinline__ float tanh_(float x) {
    float e = ex2f(x * (2.f * LOG2E));
    return 1.f - 2.f * rcpf(e + 1.f);
}

// ---------- precompute: enc part of cell0 gates ----------
// encacc[r][g] = (b_ih0[g]+b_hh0[g]) + sum_e enc[r][e] * Wih0[g][e],  r = b*Nn+n
__global__ void enc_precompute(const float* __restrict__ enc,
                               const float* __restrict__ Wih0,
                               const float* __restrict__ bih0,
                               const float* __restrict__ bhh0) {
    __shared__ float se[16][64];
    const int r0 = blockIdx.x * 16;
    const int t = threadIdx.x;
    for (int i = t; i < 16 * 64; i += 256)
        se[i >> 6][i & 63] = enc[(size_t)r0 * 64 + i];
    __syncthreads();

    const int g0 = t * 2;
    float acc0[16], acc1[16];
    const float b0 = bih0[g0] + bhh0[g0];
    const float b1 = bih0[g0 + 1] + bhh0[g0 + 1];
#pragma unroll
    for (int rr = 0; rr < 16; rr++) { acc0[rr] = b0; acc1[rr] = b1; }

#pragma unroll 4
    for (int e = 0; e < 64; e++) {
        const float w0 = Wih0[g0 * 80 + e];
        const float w1 = Wih0[(g0 + 1) * 80 + e];
#pragma unroll
        for (int rr = 0; rr < 16; rr++) {
            const float x = se[rr][e];
            acc0[rr] += x * w0;
            acc1[rr] += x * w1;
        }
    }
#pragma unroll
    for (int rr = 0; rr < 16; rr++) {
        g_encacc[(size_t)(r0 + rr) * Gg + g0]     = acc0[rr];
        g_encacc[(size_t)(r0 + rr) * Gg + g0 + 1] = acc1[rr];
    }
}

// ---------- precompute: node means ----------
__global__ void nm_precompute(const float* __restrict__ mean) {
    const int idx = blockIdx.x * 256 + threadIdx.x;   // over Bb*Nn*Oo
    if (idx >= Bb * Nn * Oo) return;
    const int o = idx & 15;
    const int rem = idx >> 4;
    const int n = rem % Nn;
    const int b = rem / Nn;
    float acc = 0.f;
#pragma unroll
    for (int f = 0; f < FUTc; f++)
        acc += mean[((size_t)(b * FUTc + f) * Nn + n) * Oo + o];
    g_nm[idx] = acc * (1.f / 12.f);
}

// ---------- main recurrent kernel: 1 CTA per batch element ----------
__global__ void __launch_bounds__(256, 1)
decoder_main(const float* __restrict__ s0v, const float* __restrict__ h0v,
             const float* __restrict__ c0v,
             const float* __restrict__ Wih0, const float* __restrict__ Whh0,
             const float* __restrict__ Whr0,
             const float* __restrict__ Wih1, const float* __restrict__ Whh1,
             const float* __restrict__ bih1, const float* __restrict__ bhh1,
             const float* __restrict__ Whr1,
             float* __restrict__ out) {
    // Shared state (all pairs duplicated {v,v} for f32x2 broadcast)
    __shared__ u64 s_x0[32];          // [0:16)=loop  [16:32)=h1   (cell0 recurrent input)
    __shared__ u64 s_x1[32];          // [0:16)=h1'   [16:32)=h2   (cell1 recurrent input)
    __shared__ u64 s_encIF[2][128];   // node-parity double buffered {pre_i, pre_f}
    __shared__ u64 s_encGO[2][128];
    __shared__ u64 s_b1IF[128];       // cell1 bias pairs
    __shared__ u64 s_b1GO[128];
    __shared__ float s_nm[2][16];
    __shared__ float s_hf[128];       // cell0 h_full
    __shared__ float s_hf2[128];      // cell1 h_full

    const int t = threadIdx.x;
    const int b = blockIdx.x;
    const int j = t & 127;
    const bool role0 = (t < 128);     // role0: cell0 + hr0; role1: cell1 + hr1 + output
    const int warp = t >> 5;
    const int lane = t & 31;

    // ---- persistent register weights ----
    u64 wIF[32], wGO[32];
    float whr[16];
    float cst;

    if (role0) {
#pragma unroll
        for (int k = 0; k < 16; k++) {
            wIF[k]      = pack2(Wih0[j * 80 + 64 + k],         Wih0[(128 + j) * 80 + 64 + k]);
            wGO[k]      = pack2(Wih0[(256 + j) * 80 + 64 + k], Wih0[(384 + j) * 80 + 64 + k]);
            wIF[16 + k] = pack2(Whh0[j * 16 + k],              Whh0[(128 + j) * 16 + k]);
            wGO[16 + k] = pack2(Whh0[(256 + j) * 16 + k],      Whh0[(384 + j) * 16 + k]);
        }
#pragma unroll
        for (int oo = 0; oo < 4; oo++)
#pragma unroll
            for (int m = 0; m < 4; m++)
                whr[oo * 4 + m] = Whr0[(4 * warp + oo) * 128 + lane + 32 * m];
        cst = c0v[j];
    } else {
#pragma unroll
        for (int k = 0; k < 16; k++) {
            wIF[k]      = pack2(Wih1[j * 16 + k],         Wih1[(128 + j) * 16 + k]);
            wGO[k]      = pack2(Wih1[(256 + j) * 16 + k], Wih1[(384 + j) * 16 + k]);
            wIF[16 + k] = pack2(Whh1[j * 16 + k],         Whh1[(128 + j) * 16 + k]);
            wGO[16 + k] = pack2(Whh1[(256 + j) * 16 + k], Whh1[(384 + j) * 16 + k]);
        }
#pragma unroll
        for (int oo = 0; oo < 4; oo++)
#pragma unroll
            for (int m = 0; m < 4; m++)
                whr[oo * 4 + m] = Whr1[(4 * (warp - 4) + oo) * 128 + lane + 32 * m];
        cst = c0v[128 + j];
        s_b1IF[j] = pack2(bih1[j] + bhh1[j],             bih1[128 + j] + bhh1[128 + j]);
        s_b1GO[j] = pack2(bih1[256 + j] + bhh1[256 + j], bih1[384 + j] + bhh1[384 + j]);
    }

    // ---- node 0 state init ----
    if (role0) {
        const float* ea = g_encacc + ((size_t)b * Nn + 0) * Gg;
        s_encIF[0][j] = pack2(ea[j], ea[128 + j]);
        s_encGO[0][j] = pack2(ea[256 + j], ea[384 + j]);
    }
    if (t < 16) {
        const float nm = g_nm[(b * Nn + 0) * Oo + t];
        s_nm[0][t] = nm;
        const float lp = s0v[t] + nm;
        s_x0[t] = pack2(lp, lp);
        const float h1i = h0v[t];      s_x0[16 + t] = pack2(h1i, h1i);
        const float h2i = h0v[16 + t]; s_x1[16 + t] = pack2(h2i, h2i);
    }
    __syncthreads();

    int n = 0, rep = 0;
    u64 aIF = 0, aGO = 0;                 // role1 accumulators persist A->C
    float pf0 = 0.f, pf1 = 0.f, pf2 = 0.f, pf3 = 0.f, pf_nm = 0.f;  // role0 prefetch

    for (int step = 0; step < TSTEPS; step++) {
        const int p = n & 1;

        // ================= Phase A =================
        if (role0) {
            // cell0 gates: enc+bias (precomputed) + [loop,h1] . W
            u64 acIF = s_encIF[p][j];
            u64 acGO = s_encGO[p][j];
#pragma unroll
            for (int k = 0; k < 32; k++) {
                const u64 x = s_x0[k];
                ffma2(acIF, x, wIF[k]);
                ffma2(acGO, x, wGO[k]);
            }
            float gi, gf, gg, go;
            unpack2(acIF, gi, gf);
            unpack2(acGO, gg, go);
            const float iv = sigm(gi), fv = sigm(gf), gv = tanh_(gg), ov = sigm(go);
            cst = fv * cst + iv * gv;
            s_hf[j] = ov * tanh_(cst);
        } else {
            // cell1 gates, h2-dependent half (h1' not ready yet)
            aIF = s_b1IF[j];
            aGO = s_b1GO[j];
#pragma unroll
            for (int k = 16; k < 32; k++) {
                const u64 x = s_x1[k];
                ffma2(aIF, x, wIF[k]);
                ffma2(aGO, x, wGO[k]);
            }
        }
        __syncthreads();   // s_hf ready

        // ================= Phase B: hr0 projection (warps 0-3) =================
        if (role0) {
            const float hv0 = s_hf[lane], hv1 = s_hf[lane + 32];
            const float hv2 = s_hf[lane + 64], hv3 = s_hf[lane + 96];
            float pr[4];
#pragma unroll
            for (int oo = 0; oo < 4; oo++)
                pr[oo] = hv0 * whr[oo * 4 + 0] + hv1 * whr[oo * 4 + 1]
                       + hv2 * whr[oo * 4 + 2] + hv3 * whr[oo * 4 + 3];
#pragma unroll
            for (int sh = 16; sh; sh >>= 1)
#pragma unroll
                for (int oo = 0; oo < 4; oo++)
                    pr[oo] += __shfl_xor_sync(0xffffffffu, pr[oo], sh);
            if (lane < 4) {
                const int o_ = 4 * warp + lane;
                const float v = pr[lane];
                s_x1[o_]      = pack2(v, v);   // h1' for cell1 (this step)
                s_x0[16 + o_] = pack2(v, v);   // h1 for cell0 (next step)
            }
        }
        __syncthreads();   // h1' ready

        // ================= Phase C =================
        if (!role0) {
            // cell1 gates, h1'-dependent half + activations
#pragma unroll
            for (int k = 0; k < 16; k++) {
                const u64 x = s_x1[k];
                ffma2(aIF, x, wIF[k]);
                ffma2(aGO, x, wGO[k]);
            }
            float gi, gf, gg, go;
            unpack2(aIF, gi, gf);
            unpack2(aGO, gg, go);
            const float iv = sigm(gi), fv = sigm(gf), gv = tanh_(gg), ov = sigm(go);
            cst = fv * cst + iv * gv;
            s_hf2[j] = ov * tanh_(cst);
        } else {
            // next-node prefetch: issue LDGs one step early, consume next step
            if (rep == 10 && n + 1 < Nn) {
                const float* ea = g_encacc + ((size_t)b * Nn + (n + 1)) * Gg;
                pf0 = ea[j]; pf1 = ea[128 + j]; pf2 = ea[256 + j]; pf3 = ea[384 + j];
                if (j < 16) pf_nm = g_nm[(b * Nn + (n + 1)) * Oo + j];
            }
            if (rep == 11 && n + 1 < Nn) {
                const int pn = (n + 1) & 1;
                s_encIF[pn][j] = pack2(pf0, pf1);
                s_encGO[pn][j] = pack2(pf2, pf3);
                if (j < 16) s_nm[pn][j] = pf_nm;
            }
        }
        __syncthreads();   // s_hf2 ready

        // ================= Phase D: hr1 + output + next-step state (warps 4-7) =================
        if (!role0) {
            const float hv0 = s_hf2[lane], hv1 = s_hf2[lane + 32];
            const float hv2 = s_hf2[lane + 64], hv3 = s_hf2[lane + 96];
            float pr[4];
#pragma unroll
            for (int oo = 0; oo < 4; oo++)
                pr[oo] = hv0 * whr[oo * 4 + 0] + hv1 * whr[oo * 4 + 1]
                       + hv2 * whr[oo * 4 + 2] + hv3 * whr[oo * 4 + 3];
#pragma unroll
            for (int sh = 16; sh; sh >>= 1)
#pragma unroll
                for (int oo = 0; oo < 4; oo++)
                    pr[oo] += __shfl_xor_sync(0xffffffffu, pr[oo], sh);
            if (lane < 4) {
                const int o_ = 4 * (warp - 4) + lane;
                const float v = pr[lane];   // h2_new
                out[(((size_t)b * FUTc + rep) * Nn + n) * Oo + o_] = v + s_nm[p][o_];
                const int nnext = (rep == 11) ? (n + 1) : n;
                const float lp = v + s_nm[nnext & 1][o_];   // loop for next step
                s_x0[o_]      = pack2(lp, lp);
                s_x1[16 + o_] = pack2(v, v);                // h2 for next step
            }
        }
        __syncthreads();   // next-step state ready

        rep++;
        if (rep == FUTc) { rep = 0; n++; }
    }
}

extern "C" void kernel_launch(void* const* d_in, const int* in_sizes, int n_in,
                              void* d_out, int out_size) {
    const float* enc  = (const float*)d_in[0];
    const float* mean = (const float*)d_in[1];
    const float* s    = (const float*)d_in[2];
    const float* h0   = (const float*)d_in[3];
    const float* c0   = (const float*)d_in[4];
    const float* Wih0 = (const float*)d_in[5];
    const float* Whh0 = (const float*)d_in[6];
    const float* bih0 = (const float*)d_in[7];
    const float* bhh0 = (const float*)d_in[8];
    const float* Whr0 = (const float*)d_in[9];
    const float* Wih1 = (const float*)d_in[10];
    const float* Whh1 = (const float*)d_in[11];
    const float* bih1 = (const float*)d_in[12];
    const float* bhh1 = (const float*)d_in[13];
    const float* Whr1 = (const float*)d_in[14];
    float* out = (float*)d_out;

    enc_precompute<<<(Bb * Nn) / 16, 256>>>(enc, Wih0, bih0, bhh0);
    nm_precompute<<<(Bb * Nn * Oo + 255) / 256, 256>>>(mean);
    decoder_main<<<Bb, 256>>>(s, h0, c0, Wih0, Whh0, Whr0,
                              Wih1, Whh1, bih1, bhh1, Whr1, out);
}